// round 1
// baseline (speedup 1.0000x reference)
#include <cuda_runtime.h>
#include <math.h>

#define B_  2
#define S_  2048
#define H_  2048
#define NH_ 16
#define HD_ 128

// Scratch (device globals: no allocation in kernel_launch allowed)
__device__ float g_q[(size_t)B_ * NH_ * S_ * HD_];
__device__ float g_k[(size_t)B_ * NH_ * S_ * HD_];
__device__ float g_v[(size_t)B_ * NH_ * S_ * HD_];
__device__ float g_attn[(size_t)B_ * S_ * H_];

// ---------------------------------------------------------------------------
// GEMM: C[M,N] = A[M,K] @ W[N,K]^T   (both row-major; "TN" w.r.t. W)
// 128x128 block tile, BK=32, 256 threads, 8x8 register tile per thread.
// EPI==0: scatter into g_q/g_k/g_v per QKV layout. EPI==1: plain store to C.
// M,N multiples of 128; K multiple of 32 (true for all 3 uses).
// ---------------------------------------------------------------------------
template <int EPI>
__global__ __launch_bounds__(256)
void gemm_tn(const float* __restrict__ A, const float* __restrict__ W,
             float* __restrict__ C, int M, int N, int K)
{
    constexpr int BM = 128, BN = 128, BK = 32;
    __shared__ float As[BK][BM + 4];   // +4 pad: float4-aligned rows, fewer conflicts
    __shared__ float Bs[BK][BN + 4];

    const int bm  = blockIdx.y * BM;
    const int bn  = blockIdx.x * BN;
    const int tid = threadIdx.x;
    const int ty  = tid >> 4;          // 0..15 -> rows ty*8..ty*8+7
    const int tx  = tid & 15;          // 0..15 -> cols tx*8..tx*8+7
    const int lrow = tid >> 3;         // 0..31
    const int lcol = (tid & 7) << 2;   // 0,4,...,28

    float acc[8][8];
    #pragma unroll
    for (int i = 0; i < 8; i++)
        #pragma unroll
        for (int j = 0; j < 8; j++) acc[i][j] = 0.f;

    const float* Aptr = A + (size_t)bm * K;
    const float* Wptr = W + (size_t)bn * K;

    for (int k0 = 0; k0 < K; k0 += BK) {
        #pragma unroll
        for (int i = 0; i < 4; i++) {
            const int r = lrow + i * 32;
            float4 va = *reinterpret_cast<const float4*>(Aptr + (size_t)r * K + k0 + lcol);
            As[lcol + 0][r] = va.x; As[lcol + 1][r] = va.y;
            As[lcol + 2][r] = va.z; As[lcol + 3][r] = va.w;
            float4 vb = *reinterpret_cast<const float4*>(Wptr + (size_t)r * K + k0 + lcol);
            Bs[lcol + 0][r] = vb.x; Bs[lcol + 1][r] = vb.y;
            Bs[lcol + 2][r] = vb.z; Bs[lcol + 3][r] = vb.w;
        }
        __syncthreads();

        #pragma unroll
        for (int kk = 0; kk < BK; kk++) {
            float ra[8], rb[8];
            *reinterpret_cast<float4*>(&ra[0]) = *reinterpret_cast<const float4*>(&As[kk][ty * 8]);
            *reinterpret_cast<float4*>(&ra[4]) = *reinterpret_cast<const float4*>(&As[kk][ty * 8 + 4]);
            *reinterpret_cast<float4*>(&rb[0]) = *reinterpret_cast<const float4*>(&Bs[kk][tx * 8]);
            *reinterpret_cast<float4*>(&rb[4]) = *reinterpret_cast<const float4*>(&Bs[kk][tx * 8 + 4]);
            #pragma unroll
            for (int i = 0; i < 8; i++)
                #pragma unroll
                for (int j = 0; j < 8; j++)
                    acc[i][j] = fmaf(ra[i], rb[j], acc[i][j]);
        }
        __syncthreads();
    }

    if (EPI == 0) {
        // QKV scatter. Tile cols [bn, bn+128) lie inside one (three, nh) slot:
        // o = three*2048 + nh*128 + hd, bn multiple of 128.
        const int three = bn >> 11;
        const int nh    = (bn & 2047) >> 7;
        float* dst = (three == 0) ? g_q : (three == 1) ? g_k : g_v;
        #pragma unroll
        for (int i = 0; i < 8; i++) {
            const int m = bm + ty * 8 + i;
            const int b = m >> 11;         // S_ = 2048
            const int s = m & 2047;
            float* o = dst + (((size_t)b * NH_ + nh) * S_ + s) * HD_ + tx * 8;
            *reinterpret_cast<float4*>(o)     = make_float4(acc[i][0], acc[i][1], acc[i][2], acc[i][3]);
            *reinterpret_cast<float4*>(o + 4) = make_float4(acc[i][4], acc[i][5], acc[i][6], acc[i][7]);
        }
    } else {
        #pragma unroll
        for (int i = 0; i < 8; i++) {
            const int m = bm + ty * 8 + i;
            float* o = C + (size_t)m * N + bn + tx * 8;
            *reinterpret_cast<float4*>(o)     = make_float4(acc[i][0], acc[i][1], acc[i][2], acc[i][3]);
            *reinterpret_cast<float4*>(o + 4) = make_float4(acc[i][4], acc[i][5], acc[i][6], acc[i][7]);
        }
    }
}

// ---------------------------------------------------------------------------
// Causal flash attention, fp32, BQ=BC=64, HD=128, 256 threads.
// Thread (ty,tx): 4 score rows (ty*4..+3) x 4 score cols (tx*4..+3),
// output tile 4 rows x 8 dims (tx*8..+7).
// Q,K stored d-major in smem (stride 68) -> conflict-free float4 inner loop.
// Skips fully-masked KV tiles (blockIdx.x+1 tiles processed).
// ---------------------------------------------------------------------------
constexpr int QK_STRIDE = 68;   // 64 + 4 pad (keeps float4 alignment: 68*4=272 % 16 == 0)
constexpr int PS_STRIDE = 68;
constexpr int ATTN_SMEM = (128 * QK_STRIDE * 2 + 64 * HD_ + 64 * PS_STRIDE) * 4; // 119808 B

__global__ __launch_bounds__(256)
void attn_kernel()
{
    extern __shared__ float sm[];
    float* Qts = sm;                          // [HD][68]  (d-major, q-rows as cols)
    float* Kts = Qts + 128 * QK_STRIDE;       // [HD][68]
    float* Vs  = Kts + 128 * QK_STRIDE;       // [64][128] (row-major)
    float* Ps  = Vs + 64 * HD_;               // [64][68]

    const int q0  = blockIdx.x * 64;
    const int h   = blockIdx.y;
    const int b   = blockIdx.z;
    const int tid = threadIdx.x;
    const int ty  = tid >> 4, tx = tid & 15;
    const int lr  = tid >> 5;                 // 0..7
    const int lc  = (tid & 31) << 2;          // 0..124 step 4

    const size_t head_off = ((size_t)b * NH_ + h) * S_ * HD_;
    const float* Qg = g_q + head_off + (size_t)q0 * HD_;
    const float* Kg = g_k + head_off;
    const float* Vg = g_v + head_off;

    const float qscale = 0.08838834764831845f;  // 1/sqrt(128)

    // Load Q (transposed, pre-scaled)
    #pragma unroll
    for (int it = 0; it < 8; it++) {
        const int r = lr + it * 8;
        float4 v = *reinterpret_cast<const float4*>(Qg + (size_t)r * HD_ + lc);
        Qts[(lc + 0) * QK_STRIDE + r] = v.x * qscale;
        Qts[(lc + 1) * QK_STRIDE + r] = v.y * qscale;
        Qts[(lc + 2) * QK_STRIDE + r] = v.z * qscale;
        Qts[(lc + 3) * QK_STRIDE + r] = v.w * qscale;
    }

    float m[4], l[4], acc[4][8];
    #pragma unroll
    for (int i = 0; i < 4; i++) {
        m[i] = -1e30f; l[i] = 0.f;
        #pragma unroll
        for (int j = 0; j < 8; j++) acc[i][j] = 0.f;
    }

    const int ntiles = blockIdx.x + 1;   // causal: only kv tiles with j0 <= q0
    for (int t = 0; t < ntiles; t++) {
        const int j0 = t * 64;
        // Load K (transposed) and V (row-major)
        #pragma unroll
        for (int it = 0; it < 8; it++) {
            const int r = lr + it * 8;
            float4 kv4 = *reinterpret_cast<const float4*>(Kg + (size_t)(j0 + r) * HD_ + lc);
            Kts[(lc + 0) * QK_STRIDE + r] = kv4.x;
            Kts[(lc + 1) * QK_STRIDE + r] = kv4.y;
            Kts[(lc + 2) * QK_STRIDE + r] = kv4.z;
            Kts[(lc + 3) * QK_STRIDE + r] = kv4.w;
            *reinterpret_cast<float4*>(Vs + r * HD_ + lc) =
                *reinterpret_cast<const float4*>(Vg + (size_t)(j0 + r) * HD_ + lc);
        }
        __syncthreads();

        // S = Q @ K^T (4x4 per thread)
        float s[4][4];
        #pragma unroll
        for (int i = 0; i < 4; i++)
            #pragma unroll
            for (int j = 0; j < 4; j++) s[i][j] = 0.f;

        #pragma unroll 8
        for (int d = 0; d < 128; d++) {
            float4 qv = *reinterpret_cast<const float4*>(Qts + d * QK_STRIDE + ty * 4);
            float4 kv = *reinterpret_cast<const float4*>(Kts + d * QK_STRIDE + tx * 4);
            const float qa[4] = {qv.x, qv.y, qv.z, qv.w};
            const float ka[4] = {kv.x, kv.y, kv.z, kv.w};
            #pragma unroll
            for (int i = 0; i < 4; i++)
                #pragma unroll
                for (int j = 0; j < 4; j++)
                    s[i][j] = fmaf(qa[i], ka[j], s[i][j]);
        }

        // Causal mask: only the diagonal tile (j0 == q0) has masked entries
        if (t == ntiles - 1) {
            #pragma unroll
            for (int i = 0; i < 4; i++)
                #pragma unroll
                for (int j = 0; j < 4; j++)
                    if (tx * 4 + j > ty * 4 + i) s[i][j] = -1e30f;
        }

        // Online softmax update (row reductions over 16 tx lanes via shfl)
        #pragma unroll
        for (int i = 0; i < 4; i++) {
            float mx = fmaxf(fmaxf(s[i][0], s[i][1]), fmaxf(s[i][2], s[i][3]));
            #pragma unroll
            for (int off = 8; off; off >>= 1)
                mx = fmaxf(mx, __shfl_xor_sync(0xffffffffu, mx, off));
            const float mnew = fmaxf(m[i], mx);
            const float corr = __expf(m[i] - mnew);
            const float p0 = __expf(s[i][0] - mnew);
            const float p1 = __expf(s[i][1] - mnew);
            const float p2 = __expf(s[i][2] - mnew);
            const float p3 = __expf(s[i][3] - mnew);
            float rs = (p0 + p1) + (p2 + p3);
            #pragma unroll
            for (int off = 8; off; off >>= 1)
                rs += __shfl_xor_sync(0xffffffffu, rs, off);
            l[i] = l[i] * corr + rs;
            m[i] = mnew;
            #pragma unroll
            for (int j = 0; j < 8; j++) acc[i][j] *= corr;
            const int pr = (ty * 4 + i) * PS_STRIDE + tx * 4;
            Ps[pr + 0] = p0; Ps[pr + 1] = p1; Ps[pr + 2] = p2; Ps[pr + 3] = p3;
        }
        __syncthreads();

        // O += P @ V
        #pragma unroll 4
        for (int c = 0; c < 64; c++) {
            float pcol[4];
            #pragma unroll
            for (int i = 0; i < 4; i++) pcol[i] = Ps[(ty * 4 + i) * PS_STRIDE + c];
            float4 v0 = *reinterpret_cast<const float4*>(Vs + c * HD_ + tx * 8);
            float4 v1 = *reinterpret_cast<const float4*>(Vs + c * HD_ + tx * 8 + 4);
            const float vv[8] = {v0.x, v0.y, v0.z, v0.w, v1.x, v1.y, v1.z, v1.w};
            #pragma unroll
            for (int i = 0; i < 4; i++)
                #pragma unroll
                for (int j = 0; j < 8; j++)
                    acc[i][j] = fmaf(pcol[i], vv[j], acc[i][j]);
        }
        __syncthreads();
    }

    // Normalize + write to g_attn[b][s][h*128 + d] (row-major [b,s,H])
    float* Og = g_attn + ((size_t)b * S_ + q0) * H_ + h * HD_;
    #pragma unroll
    for (int i = 0; i < 4; i++) {
        const float inv = 1.0f / l[i];
        const int r = ty * 4 + i;
        float4 o0 = make_float4(acc[i][0] * inv, acc[i][1] * inv, acc[i][2] * inv, acc[i][3] * inv);
        float4 o1 = make_float4(acc[i][4] * inv, acc[i][5] * inv, acc[i][6] * inv, acc[i][7] * inv);
        *reinterpret_cast<float4*>(Og + (size_t)r * H_ + tx * 8)     = o0;
        *reinterpret_cast<float4*>(Og + (size_t)r * H_ + tx * 8 + 4) = o1;
    }
}

// ---------------------------------------------------------------------------
extern "C" void kernel_launch(void* const* d_in, const int* in_sizes, int n_in,
                              void* d_out, int out_size)
{
    (void)in_sizes; (void)n_in; (void)out_size;
    const float* hidden = (const float*)d_in[0];
    // d_in[1] = attention_mask: deterministic causal mask, implemented directly.
    const float* w_pack = (const float*)d_in[2];
    const float* w_o    = (const float*)d_in[3];
    float* out = (float*)d_out;

    cudaFuncSetAttribute(attn_kernel, cudaFuncAttributeMaxDynamicSharedMemorySize, ATTN_SMEM);

    float* attn_ptr = nullptr;
    cudaGetSymbolAddress((void**)&attn_ptr, g_attn);

    const int M = B_ * S_;            // 4096
    // K1: QKV projection, scatter into q/k/v
    dim3 g1((3 * H_) / 128, M / 128); // (48, 32)
    gemm_tn<0><<<g1, 256>>>(hidden, w_pack, nullptr, M, 3 * H_, H_);

    // K2: causal flash attention
    dim3 g2(S_ / 64, NH_, B_);        // (32, 16, 2)
    attn_kernel<<<g2, 256, ATTN_SMEM>>>();

    // K3: output projection -> d_out
    dim3 g3(H_ / 128, M / 128);       // (16, 32)
    gemm_tn<1><<<g3, 256>>>(attn_ptr, w_o, out, M, H_, H_);
}

// round 3
// speedup vs baseline: 1.4778x; 1.4778x over previous
#include <cuda_runtime.h>
#include <cuda_bf16.h>
#include <math.h>
#include <stdint.h>

#define B_  2
#define S_  2048
#define H_  2048
#define NH_ 16
#define HD_ 128

// fp32 scratch
__device__ float g_q[(size_t)B_ * NH_ * S_ * HD_];
__device__ float g_k[(size_t)B_ * NH_ * S_ * HD_];
__device__ float g_v[(size_t)B_ * NH_ * S_ * HD_];
__device__ float g_attn[(size_t)B_ * S_ * H_];

// bf16 hi/lo split copies (3-term bf16 mma path)
__device__ __nv_bfloat16 g_h_hi[(size_t)B_ * S_ * H_];     // hidden
__device__ __nv_bfloat16 g_h_lo[(size_t)B_ * S_ * H_];
__device__ __nv_bfloat16 g_wp_hi[(size_t)3 * H_ * H_];     // w_pack
__device__ __nv_bfloat16 g_wp_lo[(size_t)3 * H_ * H_];
__device__ __nv_bfloat16 g_wo_hi[(size_t)H_ * H_];         // w_o
__device__ __nv_bfloat16 g_wo_lo[(size_t)H_ * H_];
__device__ __nv_bfloat16 g_ao_hi[(size_t)B_ * S_ * H_];    // attention output
__device__ __nv_bfloat16 g_ao_lo[(size_t)B_ * S_ * H_];

// ---------------------------------------------------------------------------
// split: x -> hi + lo (both bf16), vectorized
// ---------------------------------------------------------------------------
__global__ __launch_bounds__(256)
void split_kernel(const float* __restrict__ src, __nv_bfloat16* __restrict__ hi,
                  __nv_bfloat16* __restrict__ lo, int n4)
{
    const int i = blockIdx.x * blockDim.x + threadIdx.x;
    if (i >= n4) return;
    float4 v = *reinterpret_cast<const float4*>(src + (size_t)i * 4);
    __nv_bfloat16 hx = __float2bfloat16(v.x), hy = __float2bfloat16(v.y);
    __nv_bfloat16 hz = __float2bfloat16(v.z), hw = __float2bfloat16(v.w);
    __nv_bfloat16 lx = __float2bfloat16(v.x - __bfloat162float(hx));
    __nv_bfloat16 ly = __float2bfloat16(v.y - __bfloat162float(hy));
    __nv_bfloat16 lz = __float2bfloat16(v.z - __bfloat162float(hz));
    __nv_bfloat16 lw = __float2bfloat16(v.w - __bfloat162float(hw));
    __nv_bfloat162 h01, h23, l01, l23;
    h01.x = hx; h01.y = hy; h23.x = hz; h23.y = hw;
    l01.x = lx; l01.y = ly; l23.x = lz; l23.y = lw;
    *reinterpret_cast<__nv_bfloat162*>(hi + (size_t)i * 4)     = h01;
    *reinterpret_cast<__nv_bfloat162*>(hi + (size_t)i * 4 + 2) = h23;
    *reinterpret_cast<__nv_bfloat162*>(lo + (size_t)i * 4)     = l01;
    *reinterpret_cast<__nv_bfloat162*>(lo + (size_t)i * 4 + 2) = l23;
}

// ---------------------------------------------------------------------------
// mma.sync helpers
// ---------------------------------------------------------------------------
__device__ __forceinline__ uint32_t smem_u32(const void* p) {
    uint32_t a;
    asm("{ .reg .u64 t; cvta.to.shared.u64 t, %1; cvt.u32.u64 %0, t; }" : "=r"(a) : "l"(p));
    return a;
}
#define LDSM_X4(r, addr) \
    asm volatile("ldmatrix.sync.aligned.m8n8.x4.shared.b16 {%0,%1,%2,%3}, [%4];" \
        : "=r"((r)[0]), "=r"((r)[1]), "=r"((r)[2]), "=r"((r)[3]) : "r"(addr))

__device__ __forceinline__ void mma_bf16(float* c, const uint32_t* a, uint32_t b0, uint32_t b1) {
    asm volatile("mma.sync.aligned.m16n8k16.row.col.f32.bf16.bf16.f32 "
                 "{%0,%1,%2,%3}, {%4,%5,%6,%7}, {%8,%9}, {%0,%1,%2,%3};"
                 : "+f"(c[0]), "+f"(c[1]), "+f"(c[2]), "+f"(c[3])
                 : "r"(a[0]), "r"(a[1]), "r"(a[2]), "r"(a[3]), "r"(b0), "r"(b1));
}

// ---------------------------------------------------------------------------
// GEMM via bf16 mma.sync, 3-term split: C = A @ W^T (A,W given as bf16 hi/lo)
// CTA 128x128, BK=32, 256 threads, 8 warps (4m x 2n), warp tile 32x64.
// Smem: [2 stages][4 comps: Ahi,Alo,Bhi,Blo][128 rows][40 bf16] (pad 40 vs 32).
// EPI==0: scatter into g_q/g_k/g_v. EPI==1: plain store to C.
// ---------------------------------------------------------------------------
constexpr int LDS_B = 40;                       // smem row stride in bf16
constexpr int COMP_ELEMS = 128 * LDS_B;         // 5120
constexpr int GEMM_SMEM = 2 * 4 * COMP_ELEMS * 2;  // 81920 bytes

template <int EPI>
__global__ __launch_bounds__(256)
void gemm_mma(const __nv_bfloat16* __restrict__ Ahi, const __nv_bfloat16* __restrict__ Alo,
              const __nv_bfloat16* __restrict__ Bhi, const __nv_bfloat16* __restrict__ Blo,
              float* __restrict__ C, int N, int K)
{
    extern __shared__ __nv_bfloat16 sm[];
    const int bm = blockIdx.y * 128, bn = blockIdx.x * 128;
    const int tid = threadIdx.x, wid = tid >> 5, lane = tid & 31;
    const int wm = wid >> 1, wn = wid & 1;

    const __nv_bfloat16* gp[4] = { Ahi + (size_t)bm * K, Alo + (size_t)bm * K,
                                   Bhi + (size_t)bn * K, Blo + (size_t)bn * K };

    float acc[2][8][4];
    #pragma unroll
    for (int i = 0; i < 2; i++)
        #pragma unroll
        for (int j = 0; j < 8; j++)
            #pragma unroll
            for (int k = 0; k < 4; k++) acc[i][j][k] = 0.f;

    const uint32_t smbase = smem_u32(sm);
    const int lrow = lane & 15;            // ldmatrix row within 16-block
    const int lcol = (lane >> 4) * 8;      // ldmatrix k-half select

    // gmem load target: thread t covers 2 uint4 per comp
    const int r0l = (tid * 2) >> 2;        // row for j=0
    const int q0l = (tid * 2) & 3;
    const int r1l = (tid * 2 + 1) >> 2;
    const int q1l = (tid * 2 + 1) & 3;

    uint4 pf[8];
    auto gload = [&](int k0) {
        #pragma unroll
        for (int c = 0; c < 4; c++) {
            pf[c * 2 + 0] = *reinterpret_cast<const uint4*>(gp[c] + (size_t)r0l * K + k0 + q0l * 8);
            pf[c * 2 + 1] = *reinterpret_cast<const uint4*>(gp[c] + (size_t)r1l * K + k0 + q1l * 8);
        }
    };
    auto sstore = [&](int s) {
        #pragma unroll
        for (int c = 0; c < 4; c++) {
            __nv_bfloat16* base = sm + (s * 4 + c) * COMP_ELEMS;
            *reinterpret_cast<uint4*>(base + r0l * LDS_B + q0l * 8) = pf[c * 2 + 0];
            *reinterpret_cast<uint4*>(base + r1l * LDS_B + q1l * 8) = pf[c * 2 + 1];
        }
    };

    const int niter = K >> 5;
    gload(0); sstore(0);
    __syncthreads();

    for (int it = 0; it < niter; it++) {
        const int s = it & 1;
        if (it + 1 < niter) gload((it + 1) << 5);

        const uint32_t stA = smbase + (uint32_t)((s * 4 + 0) * COMP_ELEMS) * 2;
        const uint32_t stAl = smbase + (uint32_t)((s * 4 + 1) * COMP_ELEMS) * 2;
        const uint32_t stB = smbase + (uint32_t)((s * 4 + 2) * COMP_ELEMS) * 2;
        const uint32_t stBl = smbase + (uint32_t)((s * 4 + 3) * COMP_ELEMS) * 2;

        #pragma unroll
        for (int kk = 0; kk < 32; kk += 16) {
            uint32_t ah[2][4], al[2][4], bh[4][4], bl[4][4];
            #pragma unroll
            for (int mi = 0; mi < 2; mi++) {
                const uint32_t off = (uint32_t)(((wm * 32 + mi * 16 + lrow) * LDS_B + kk + lcol) * 2);
                LDSM_X4(ah[mi], stA + off);
                LDSM_X4(al[mi], stAl + off);
            }
            #pragma unroll
            for (int ni = 0; ni < 4; ni++) {
                const uint32_t off = (uint32_t)(((wn * 64 + ni * 16 + lrow) * LDS_B + kk + lcol) * 2);
                LDSM_X4(bh[ni], stB + off);
                LDSM_X4(bl[ni], stBl + off);
            }
            #pragma unroll
            for (int mi = 0; mi < 2; mi++)
                #pragma unroll
                for (int nj = 0; nj < 8; nj++) {
                    const int ni = nj >> 1, hf = nj & 1;
                    mma_bf16(acc[mi][nj], ah[mi], bh[ni][hf], bh[ni][hf + 2]);
                    mma_bf16(acc[mi][nj], ah[mi], bl[ni][hf], bl[ni][hf + 2]);
                    mma_bf16(acc[mi][nj], al[mi], bh[ni][hf], bh[ni][hf + 2]);
                }
        }
        if (it + 1 < niter) sstore(s ^ 1);
        __syncthreads();
    }

    // epilogue
    const int g = lane >> 2, t = lane & 3;
    #pragma unroll
    for (int mi = 0; mi < 2; mi++) {
        const int mrow = bm + wm * 32 + mi * 16 + g;     // and mrow+8
        #pragma unroll
        for (int nj = 0; nj < 8; nj++) {
            const int col = wn * 64 + nj * 8 + 2 * t;
            float2 v0 = make_float2(acc[mi][nj][0], acc[mi][nj][1]);
            float2 v1 = make_float2(acc[mi][nj][2], acc[mi][nj][3]);
            if (EPI == 0) {
                const int three = bn >> 11;
                const int nh    = (bn & 2047) >> 7;
                float* dst = (three == 0) ? g_q : (three == 1) ? g_k : g_v;
                const int b0i = mrow >> 11, s0i = mrow & 2047;
                const int b1i = (mrow + 8) >> 11, s1i = (mrow + 8) & 2047;
                *reinterpret_cast<float2*>(dst + (((size_t)b0i * NH_ + nh) * S_ + s0i) * HD_ + col) = v0;
                *reinterpret_cast<float2*>(dst + (((size_t)b1i * NH_ + nh) * S_ + s1i) * HD_ + col) = v1;
            } else {
                *reinterpret_cast<float2*>(C + (size_t)mrow * N + bn + col) = v0;
                *reinterpret_cast<float2*>(C + (size_t)(mrow + 8) * N + bn + col) = v1;
            }
        }
    }
}

// ---------------------------------------------------------------------------
// Causal flash attention, fp32, BQ=BC=64, HD=128, 256 threads. (unchanged)
// ---------------------------------------------------------------------------
constexpr int QK_STRIDE = 68;
constexpr int PS_STRIDE = 68;
constexpr int ATTN_SMEM = (128 * QK_STRIDE * 2 + 64 * HD_ + 64 * PS_STRIDE) * 4;

__global__ __launch_bounds__(256)
void attn_kernel()
{
    extern __shared__ float smf[];
    float* Qts = smf;
    float* Kts = Qts + 128 * QK_STRIDE;
    float* Vs  = Kts + 128 * QK_STRIDE;
    float* Ps  = Vs + 64 * HD_;

    const int q0  = blockIdx.x * 64;
    const int h   = blockIdx.y;
    const int b   = blockIdx.z;
    const int tid = threadIdx.x;
    const int ty  = tid >> 4, tx = tid & 15;
    const int lr  = tid >> 5;
    const int lc  = (tid & 31) << 2;

    const size_t head_off = ((size_t)b * NH_ + h) * S_ * HD_;
    const float* Qg = g_q + head_off + (size_t)q0 * HD_;
    const float* Kg = g_k + head_off;
    const float* Vg = g_v + head_off;

    const float qscale = 0.08838834764831845f;

    #pragma unroll
    for (int it = 0; it < 8; it++) {
        const int r = lr + it * 8;
        float4 v = *reinterpret_cast<const float4*>(Qg + (size_t)r * HD_ + lc);
        Qts[(lc + 0) * QK_STRIDE + r] = v.x * qscale;
        Qts[(lc + 1) * QK_STRIDE + r] = v.y * qscale;
        Qts[(lc + 2) * QK_STRIDE + r] = v.z * qscale;
        Qts[(lc + 3) * QK_STRIDE + r] = v.w * qscale;
    }

    float m[4], l[4], acc[4][8];
    #pragma unroll
    for (int i = 0; i < 4; i++) {
        m[i] = -1e30f; l[i] = 0.f;
        #pragma unroll
        for (int j = 0; j < 8; j++) acc[i][j] = 0.f;
    }

    const int ntiles = blockIdx.x + 1;
    for (int t = 0; t < ntiles; t++) {
        const int j0 = t * 64;
        #pragma unroll
        for (int it = 0; it < 8; it++) {
            const int r = lr + it * 8;
            float4 kv4 = *reinterpret_cast<const float4*>(Kg + (size_t)(j0 + r) * HD_ + lc);
            Kts[(lc + 0) * QK_STRIDE + r] = kv4.x;
            Kts[(lc + 1) * QK_STRIDE + r] = kv4.y;
            Kts[(lc + 2) * QK_STRIDE + r] = kv4.z;
            Kts[(lc + 3) * QK_STRIDE + r] = kv4.w;
            *reinterpret_cast<float4*>(Vs + r * HD_ + lc) =
                *reinterpret_cast<const float4*>(Vg + (size_t)(j0 + r) * HD_ + lc);
        }
        __syncthreads();

        float s[4][4];
        #pragma unroll
        for (int i = 0; i < 4; i++)
            #pragma unroll
            for (int j = 0; j < 4; j++) s[i][j] = 0.f;

        #pragma unroll 8
        for (int d = 0; d < 128; d++) {
            float4 qv = *reinterpret_cast<const float4*>(Qts + d * QK_STRIDE + ty * 4);
            float4 kv = *reinterpret_cast<const float4*>(Kts + d * QK_STRIDE + tx * 4);
            const float qa[4] = {qv.x, qv.y, qv.z, qv.w};
            const float ka[4] = {kv.x, kv.y, kv.z, kv.w};
            #pragma unroll
            for (int i = 0; i < 4; i++)
                #pragma unroll
                for (int j = 0; j < 4; j++)
                    s[i][j] = fmaf(qa[i], ka[j], s[i][j]);
        }

        if (t == ntiles - 1) {
            #pragma unroll
            for (int i = 0; i < 4; i++)
                #pragma unroll
                for (int j = 0; j < 4; j++)
                    if (tx * 4 + j > ty * 4 + i) s[i][j] = -1e30f;
        }

        #pragma unroll
        for (int i = 0; i < 4; i++) {
            float mx = fmaxf(fmaxf(s[i][0], s[i][1]), fmaxf(s[i][2], s[i][3]));
            #pragma unroll
            for (int off = 8; off; off >>= 1)
                mx = fmaxf(mx, __shfl_xor_sync(0xffffffffu, mx, off));
            const float mnew = fmaxf(m[i], mx);
            const float corr = __expf(m[i] - mnew);
            const float p0 = __expf(s[i][0] - mnew);
            const float p1 = __expf(s[i][1] - mnew);
            const float p2 = __expf(s[i][2] - mnew);
            const float p3 = __expf(s[i][3] - mnew);
            float rs = (p0 + p1) + (p2 + p3);
            #pragma unroll
            for (int off = 8; off; off >>= 1)
                rs += __shfl_xor_sync(0xffffffffu, rs, off);
            l[i] = l[i] * corr + rs;
            m[i] = mnew;
            #pragma unroll
            for (int j = 0; j < 8; j++) acc[i][j] *= corr;
            const int pr = (ty * 4 + i) * PS_STRIDE + tx * 4;
            Ps[pr + 0] = p0; Ps[pr + 1] = p1; Ps[pr + 2] = p2; Ps[pr + 3] = p3;
        }
        __syncthreads();

        #pragma unroll 4
        for (int c = 0; c < 64; c++) {
            float pcol[4];
            #pragma unroll
            for (int i = 0; i < 4; i++) pcol[i] = Ps[(ty * 4 + i) * PS_STRIDE + c];
            float4 v0 = *reinterpret_cast<const float4*>(Vs + c * HD_ + tx * 8);
            float4 v1 = *reinterpret_cast<const float4*>(Vs + c * HD_ + tx * 8 + 4);
            const float vv[8] = {v0.x, v0.y, v0.z, v0.w, v1.x, v1.y, v1.z, v1.w};
            #pragma unroll
            for (int i = 0; i < 4; i++)
                #pragma unroll
                for (int j = 0; j < 8; j++)
                    acc[i][j] = fmaf(pcol[i], vv[j], acc[i][j]);
        }
        __syncthreads();
    }

    float* Og = g_attn + ((size_t)b * S_ + q0) * H_ + h * HD_;
    #pragma unroll
    for (int i = 0; i < 4; i++) {
        const float inv = 1.0f / l[i];
        const int r = ty * 4 + i;
        float4 o0 = make_float4(acc[i][0] * inv, acc[i][1] * inv, acc[i][2] * inv, acc[i][3] * inv);
        float4 o1 = make_float4(acc[i][4] * inv, acc[i][5] * inv, acc[i][6] * inv, acc[i][7] * inv);
        *reinterpret_cast<float4*>(Og + (size_t)r * H_ + tx * 8)     = o0;
        *reinterpret_cast<float4*>(Og + (size_t)r * H_ + tx * 8 + 4) = o1;
    }
}

// ---------------------------------------------------------------------------
extern "C" void kernel_launch(void* const* d_in, const int* in_sizes, int n_in,
                              void* d_out, int out_size)
{
    (void)in_sizes; (void)n_in; (void)out_size;
    const float* hidden = (const float*)d_in[0];
    // d_in[1] = attention_mask: deterministic causal mask, implemented directly.
    const float* w_pack = (const float*)d_in[2];
    const float* w_o    = (const float*)d_in[3];
    float* out = (float*)d_out;

    cudaFuncSetAttribute(gemm_mma<0>, cudaFuncAttributeMaxDynamicSharedMemorySize, GEMM_SMEM);
    cudaFuncSetAttribute(gemm_mma<1>, cudaFuncAttributeMaxDynamicSharedMemorySize, GEMM_SMEM);
    cudaFuncSetAttribute(attn_kernel, cudaFuncAttributeMaxDynamicSharedMemorySize, ATTN_SMEM);

    float* attn_ptr = nullptr;
    cudaGetSymbolAddress((void**)&attn_ptr, g_attn);
    __nv_bfloat16 *h_hi, *h_lo, *wp_hi, *wp_lo, *wo_hi, *wo_lo, *ao_hi, *ao_lo;
    cudaGetSymbolAddress((void**)&h_hi,  g_h_hi);  cudaGetSymbolAddress((void**)&h_lo,  g_h_lo);
    cudaGetSymbolAddress((void**)&wp_hi, g_wp_hi); cudaGetSymbolAddress((void**)&wp_lo, g_wp_lo);
    cudaGetSymbolAddress((void**)&wo_hi, g_wo_hi); cudaGetSymbolAddress((void**)&wo_lo, g_wo_lo);
    cudaGetSymbolAddress((void**)&ao_hi, g_ao_hi); cudaGetSymbolAddress((void**)&ao_lo, g_ao_lo);

    const int M = B_ * S_;                       // 4096
    const int n_hidden = M * H_;                 // 8.39M
    const int n_wp = 3 * H_ * H_;                // 12.58M
    const int n_wo = H_ * H_;                    // 4.19M

    // splits (fp32 -> bf16 hi/lo)
    split_kernel<<<(n_hidden / 4 + 255) / 256, 256>>>(hidden, h_hi, h_lo, n_hidden / 4);
    split_kernel<<<(n_wp / 4 + 255) / 256, 256>>>(w_pack, wp_hi, wp_lo, n_wp / 4);
    split_kernel<<<(n_wo / 4 + 255) / 256, 256>>>(w_o, wo_hi, wo_lo, n_wo / 4);

    // K1: QKV projection (bf16 mma, 3-term), scatter into q/k/v
    dim3 g1((3 * H_) / 128, M / 128);            // (48, 32)
    gemm_mma<0><<<g1, 256, GEMM_SMEM>>>(h_hi, h_lo, wp_hi, wp_lo, nullptr, 3 * H_, H_);

    // K2: causal flash attention (fp32)
    dim3 g2(S_ / 64, NH_, B_);                   // (32, 16, 2)
    attn_kernel<<<g2, 256, ATTN_SMEM>>>();

    // split attention output
    split_kernel<<<(n_hidden / 4 + 255) / 256, 256>>>(attn_ptr, ao_hi, ao_lo, n_hidden / 4);

    // K3: output projection (bf16 mma, 3-term) -> d_out
    dim3 g3(H_ / 128, M / 128);                  // (16, 32)
    gemm_mma<1><<<g3, 256, GEMM_SMEM>>>(ao_hi, ao_lo, wo_hi, wo_lo, out, H_, H_);
}

// round 4
// speedup vs baseline: 2.6029x; 1.7614x over previous
#include <cuda_runtime.h>
#include <cuda_bf16.h>
#include <math.h>
#include <stdint.h>

#define B_  2
#define S_  2048
#define H_  2048
#define NH_ 16
#define HD_ 128

// bf16 hi/lo split buffers
__device__ __nv_bfloat16 g_h_hi[(size_t)B_ * S_ * H_];
__device__ __nv_bfloat16 g_h_lo[(size_t)B_ * S_ * H_];
__device__ __nv_bfloat16 g_wp_hi[(size_t)3 * H_ * H_];
__device__ __nv_bfloat16 g_wp_lo[(size_t)3 * H_ * H_];
__device__ __nv_bfloat16 g_wo_hi[(size_t)H_ * H_];
__device__ __nv_bfloat16 g_wo_lo[(size_t)H_ * H_];
__device__ __nv_bfloat16 g_q_hi[(size_t)B_ * NH_ * S_ * HD_];
__device__ __nv_bfloat16 g_q_lo[(size_t)B_ * NH_ * S_ * HD_];
__device__ __nv_bfloat16 g_k_hi[(size_t)B_ * NH_ * S_ * HD_];
__device__ __nv_bfloat16 g_k_lo[(size_t)B_ * NH_ * S_ * HD_];
__device__ __nv_bfloat16 g_v_hi[(size_t)B_ * NH_ * S_ * HD_];
__device__ __nv_bfloat16 g_v_lo[(size_t)B_ * NH_ * S_ * HD_];
__device__ __nv_bfloat16 g_ao_hi[(size_t)B_ * S_ * H_];
__device__ __nv_bfloat16 g_ao_lo[(size_t)B_ * S_ * H_];

// ---------------------------------------------------------------------------
// helpers
// ---------------------------------------------------------------------------
__device__ __forceinline__ uint32_t smem_u32(const void* p) {
    uint32_t a;
    asm("{ .reg .u64 t; cvta.to.shared.u64 t, %1; cvt.u32.u64 %0, t; }" : "=r"(a) : "l"(p));
    return a;
}
#define LDSM_X4(r, addr) \
    asm volatile("ldmatrix.sync.aligned.m8n8.x4.shared.b16 {%0,%1,%2,%3}, [%4];" \
        : "=r"((r)[0]), "=r"((r)[1]), "=r"((r)[2]), "=r"((r)[3]) : "r"(addr))
#define LDSM_X4_T(r, addr) \
    asm volatile("ldmatrix.sync.aligned.m8n8.x4.trans.shared.b16 {%0,%1,%2,%3}, [%4];" \
        : "=r"((r)[0]), "=r"((r)[1]), "=r"((r)[2]), "=r"((r)[3]) : "r"(addr))

__device__ __forceinline__ void mma_bf16(float* c, const uint32_t* a, uint32_t b0, uint32_t b1) {
    asm volatile("mma.sync.aligned.m16n8k16.row.col.f32.bf16.bf16.f32 "
                 "{%0,%1,%2,%3}, {%4,%5,%6,%7}, {%8,%9}, {%0,%1,%2,%3};"
                 : "+f"(c[0]), "+f"(c[1]), "+f"(c[2]), "+f"(c[3])
                 : "r"(a[0]), "r"(a[1]), "r"(a[2]), "r"(a[3]), "r"(b0), "r"(b1));
}
__device__ __forceinline__ void cp16(uint32_t dst, const void* src) {
    asm volatile("cp.async.cg.shared.global [%0], [%1], 16;" :: "r"(dst), "l"(src) : "memory");
}
#define CP_COMMIT() asm volatile("cp.async.commit_group;" ::: "memory")
template <int N> __device__ __forceinline__ void cp_wait() {
    asm volatile("cp.async.wait_group %0;" :: "n"(N) : "memory");
}
__device__ __forceinline__ void pack_hilo(float x, float y, uint32_t& hi, uint32_t& lo) {
    __nv_bfloat162 h = __float22bfloat162_rn(make_float2(x, y));
    __nv_bfloat162 l = __float22bfloat162_rn(make_float2(x - __bfloat162float(h.x),
                                                         y - __bfloat162float(h.y)));
    hi = *reinterpret_cast<uint32_t*>(&h);
    lo = *reinterpret_cast<uint32_t*>(&l);
}

// ---------------------------------------------------------------------------
// split: fp32 -> bf16 hi + lo
// ---------------------------------------------------------------------------
__global__ __launch_bounds__(256)
void split_kernel(const float* __restrict__ src, __nv_bfloat16* __restrict__ hi,
                  __nv_bfloat16* __restrict__ lo, int n4)
{
    const int i = blockIdx.x * blockDim.x + threadIdx.x;
    if (i >= n4) return;
    float4 v = *reinterpret_cast<const float4*>(src + (size_t)i * 4);
    uint32_t h01, l01, h23, l23;
    pack_hilo(v.x, v.y, h01, l01);
    pack_hilo(v.z, v.w, h23, l23);
    *reinterpret_cast<uint2*>(hi + (size_t)i * 4) = make_uint2(h01, h23);
    *reinterpret_cast<uint2*>(lo + (size_t)i * 4) = make_uint2(l01, l23);
}

// ---------------------------------------------------------------------------
// GEMM via bf16 mma.sync 3-term, cp.async, CTA 128x64, BK=32, 256 thr, 2 CTA/SM
// EPI==0: emit q (scaled)/k/v as bf16 hi/lo. EPI==1: fp32 store to C.
// ---------------------------------------------------------------------------
constexpr int GLD = 40;                     // smem row stride (bf16) for 32-col rows
constexpr int GA_EL = 128 * GLD;            // 5120 per A comp
constexpr int GB_EL = 64 * GLD;             // 2560 per B comp
constexpr int GSTAGE_EL = 2 * GA_EL + 2 * GB_EL;   // 15360
constexpr int GEMM_SMEM = 2 * GSTAGE_EL * 2;       // 61440 B

template <int EPI>
__global__ __launch_bounds__(256, 2)
void gemm_mma(const __nv_bfloat16* __restrict__ Ahi, const __nv_bfloat16* __restrict__ Alo,
              const __nv_bfloat16* __restrict__ Bhi, const __nv_bfloat16* __restrict__ Blo,
              float* __restrict__ C, int N, int K)
{
    extern __shared__ __nv_bfloat16 sm[];
    const int bm = blockIdx.y * 128, bn = blockIdx.x * 64;
    const int tid = threadIdx.x, wid = tid >> 5, lane = tid & 31;
    const int wm = wid >> 1, wn = wid & 1;
    const int lrow = lane & 15, lcol8 = (lane >> 4) * 8;
    const uint32_t smb = smem_u32(sm);

    const __nv_bfloat16* gA[2] = { Ahi + (size_t)bm * K, Alo + (size_t)bm * K };
    const __nv_bfloat16* gB[2] = { Bhi + (size_t)bn * K, Blo + (size_t)bn * K };

    auto load_stage = [&](int k0, int s) {
        const uint32_t sb = smb + (uint32_t)(s * GSTAGE_EL) * 2;
        #pragma unroll
        for (int c = 0; c < 2; c++)
            #pragma unroll
            for (int i = 0; i < 2; i++) {
                const int idx = tid + i * 256;
                const int r = idx >> 2, q = idx & 3;
                cp16(sb + (uint32_t)(c * GA_EL + r * GLD + q * 8) * 2,
                     gA[c] + (size_t)r * K + k0 + q * 8);
            }
        #pragma unroll
        for (int c = 0; c < 2; c++) {
            const int r = tid >> 2, q = tid & 3;
            cp16(sb + (uint32_t)(2 * GA_EL + c * GB_EL + r * GLD + q * 8) * 2,
                 gB[c] + (size_t)r * K + k0 + q * 8);
        }
        CP_COMMIT();
    };

    float acc[2][4][4];
    #pragma unroll
    for (int i = 0; i < 2; i++)
        #pragma unroll
        for (int j = 0; j < 4; j++)
            #pragma unroll
            for (int k = 0; k < 4; k++) acc[i][j][k] = 0.f;

    const int niter = K >> 5;
    load_stage(0, 0);

    for (int it = 0; it < niter; it++) {
        const int s = it & 1;
        if (it + 1 < niter) { load_stage((it + 1) << 5, s ^ 1); cp_wait<1>(); }
        else                { cp_wait<0>(); }
        __syncthreads();

        const uint32_t sb = smb + (uint32_t)(s * GSTAGE_EL) * 2;
        #pragma unroll
        for (int kk = 0; kk < 32; kk += 16) {
            uint32_t bh4[2][4], bl4[2][4];
            #pragma unroll
            for (int nb = 0; nb < 2; nb++) {
                const uint32_t ok = sb + (uint32_t)((2 * GA_EL) + (wn * 32 + nb * 16 + lrow) * GLD + kk + lcol8) * 2;
                LDSM_X4(bh4[nb], ok);
                LDSM_X4(bl4[nb], ok + (uint32_t)GB_EL * 2);
            }
            #pragma unroll
            for (int mi = 0; mi < 2; mi++) {
                uint32_t ah[4], al[4];
                const uint32_t oa = sb + (uint32_t)((wm * 32 + mi * 16 + lrow) * GLD + kk + lcol8) * 2;
                LDSM_X4(ah, oa);
                LDSM_X4(al, oa + (uint32_t)GA_EL * 2);
                #pragma unroll
                for (int nb = 0; nb < 2; nb++)
                    #pragma unroll
                    for (int hf = 0; hf < 2; hf++) {
                        const int nj = nb * 2 + hf;
                        mma_bf16(acc[mi][nj], ah, bh4[nb][hf], bh4[nb][hf + 2]);
                        mma_bf16(acc[mi][nj], ah, bl4[nb][hf], bl4[nb][hf + 2]);
                        mma_bf16(acc[mi][nj], al, bh4[nb][hf], bh4[nb][hf + 2]);
                    }
            }
        }
        __syncthreads();
    }

    // epilogue
    const int g = lane >> 2, t4 = lane & 3;
    if (EPI == 0) {
        const int three = bn >> 11;
        const int within = bn & 2047;
        const int nh = within >> 7;
        const int cb = within & 127;
        __nv_bfloat16 *dh, *dl;
        if (three == 0)      { dh = g_q_hi; dl = g_q_lo; }
        else if (three == 1) { dh = g_k_hi; dl = g_k_lo; }
        else                 { dh = g_v_hi; dl = g_v_lo; }
        const float scl = (three == 0) ? 0.08838834764831845f : 1.0f;
        #pragma unroll
        for (int mi = 0; mi < 2; mi++)
            #pragma unroll
            for (int nj = 0; nj < 4; nj++) {
                const int col = cb + wn * 32 + nj * 8 + 2 * t4;
                #pragma unroll
                for (int half = 0; half < 2; half++) {
                    const int m = bm + wm * 32 + mi * 16 + g + half * 8;
                    const int bi = m >> 11, si = m & 2047;
                    const size_t o = (((size_t)bi * NH_ + nh) * S_ + si) * HD_ + col;
                    uint32_t hv, lv;
                    pack_hilo(acc[mi][nj][half * 2] * scl, acc[mi][nj][half * 2 + 1] * scl, hv, lv);
                    *reinterpret_cast<uint32_t*>(dh + o) = hv;
                    *reinterpret_cast<uint32_t*>(dl + o) = lv;
                }
            }
    } else {
        #pragma unroll
        for (int mi = 0; mi < 2; mi++)
            #pragma unroll
            for (int nj = 0; nj < 4; nj++) {
                const int col = bn + wn * 32 + nj * 8 + 2 * t4;
                const int m0r = bm + wm * 32 + mi * 16 + g;
                *reinterpret_cast<float2*>(C + (size_t)m0r * N + col) =
                    make_float2(acc[mi][nj][0], acc[mi][nj][1]);
                *reinterpret_cast<float2*>(C + (size_t)(m0r + 8) * N + col) =
                    make_float2(acc[mi][nj][2], acc[mi][nj][3]);
            }
    }
}

// ---------------------------------------------------------------------------
// Causal flash attention via bf16 mma.sync 3-term. BQ=128, BC=64, 256 threads.
// Q/K/V bf16 hi/lo from GEMM<0>. Output bf16 hi/lo for GEMM<1>.
// ---------------------------------------------------------------------------
constexpr int LDA_ = 136;             // bf16 stride for 128-col rows
constexpr int QEL = 128 * LDA_;       // 17408
constexpr int KEL = 64 * LDA_;        // 8704
constexpr int OFF_K0 = 2 * QEL;
constexpr int OFF_V0 = 2 * QEL + 4 * KEL;
constexpr int ATTN_SMEM = (2 * QEL + 8 * KEL) * 2;   // 208896 B

__global__ __launch_bounds__(256)
void attn_mma()
{
    extern __shared__ __nv_bfloat16 sm[];
    const int q0 = blockIdx.x * 128;
    const int h = blockIdx.y, b = blockIdx.z;
    const int tid = threadIdx.x, wid = tid >> 5, lane = tid & 31;
    const int g = lane >> 2, t4 = lane & 3;
    const int lrow = lane & 15, lcol8 = (lane >> 4) * 8;
    const uint32_t smb = smem_u32(sm);

    const size_t hoff = ((size_t)b * NH_ + h) * S_ * HD_;
    const __nv_bfloat16* qh = g_q_hi + hoff + (size_t)q0 * HD_;
    const __nv_bfloat16* ql = g_q_lo + hoff + (size_t)q0 * HD_;
    const __nv_bfloat16* kh = g_k_hi + hoff;
    const __nv_bfloat16* kl = g_k_lo + hoff;
    const __nv_bfloat16* vhp = g_v_hi + hoff;
    const __nv_bfloat16* vlp = g_v_lo + hoff;

    // load Q hi/lo (plain 16B)
    #pragma unroll
    for (int i = 0; i < 8; i++) {
        const int idx = tid + i * 256;
        const int r = idx >> 4, q = idx & 15;
        *reinterpret_cast<uint4*>(sm + r * LDA_ + q * 8) =
            *reinterpret_cast<const uint4*>(qh + (size_t)r * HD_ + q * 8);
        *reinterpret_cast<uint4*>(sm + QEL + r * LDA_ + q * 8) =
            *reinterpret_cast<const uint4*>(ql + (size_t)r * HD_ + q * 8);
    }

    auto load_kv = [&](int t, int s) {
        const int j0 = t * 64;
        const uint32_t sk = smb + (uint32_t)(OFF_K0 + s * 2 * KEL) * 2;
        const uint32_t sv = smb + (uint32_t)(OFF_V0 + s * 2 * KEL) * 2;
        #pragma unroll
        for (int i = 0; i < 4; i++) {
            const int idx = tid + i * 256;
            const int r = idx >> 4, q = idx & 15;
            const uint32_t so = (uint32_t)(r * LDA_ + q * 8) * 2;
            const size_t go = (size_t)(j0 + r) * HD_ + q * 8;
            cp16(sk + so,                      kh + go);
            cp16(sk + (uint32_t)KEL * 2 + so,  kl + go);
            cp16(sv + so,                      vhp + go);
            cp16(sv + (uint32_t)KEL * 2 + so,  vlp + go);
        }
        CP_COMMIT();
    };

    const int ntiles = q0 / 64 + 2;
    load_kv(0, 0);

    float m0 = -1e30f, m1 = -1e30f, l0 = 0.f, l1 = 0.f;
    float oa[16][4];
    #pragma unroll
    for (int f = 0; f < 16; f++)
        #pragma unroll
        for (int k = 0; k < 4; k++) oa[f][k] = 0.f;

    const int rg0 = q0 + wid * 16 + g;
    const int rg1 = rg0 + 8;

    for (int t = 0; t < ntiles; t++) {
        const int st = t & 1;
        if (t + 1 < ntiles) { load_kv(t + 1, st ^ 1); cp_wait<1>(); }
        else                { cp_wait<0>(); }
        __syncthreads();

        const uint32_t sk = smb + (uint32_t)(OFF_K0 + st * 2 * KEL) * 2;
        const uint32_t sv = smb + (uint32_t)(OFF_V0 + st * 2 * KEL) * 2;

        // ---- S = Q K^T (3-term) ----
        float sc[8][4];
        #pragma unroll
        for (int nj = 0; nj < 8; nj++)
            #pragma unroll
            for (int k = 0; k < 4; k++) sc[nj][k] = 0.f;

        #pragma unroll
        for (int kc = 0; kc < 8; kc++) {
            uint32_t ah[4], al[4];
            const uint32_t oq = smb + (uint32_t)((wid * 16 + lrow) * LDA_ + kc * 16 + lcol8) * 2;
            LDSM_X4(ah, oq);
            LDSM_X4(al, oq + (uint32_t)QEL * 2);
            #pragma unroll
            for (int nb = 0; nb < 4; nb++) {
                uint32_t bh4[4], bl4[4];
                const uint32_t ok = sk + (uint32_t)((nb * 16 + lrow) * LDA_ + kc * 16 + lcol8) * 2;
                LDSM_X4(bh4, ok);
                LDSM_X4(bl4, ok + (uint32_t)KEL * 2);
                #pragma unroll
                for (int hf = 0; hf < 2; hf++) {
                    const int nj = nb * 2 + hf;
                    mma_bf16(sc[nj], ah, bh4[hf], bh4[hf + 2]);
                    mma_bf16(sc[nj], ah, bl4[hf], bl4[hf + 2]);
                    mma_bf16(sc[nj], al, bh4[hf], bh4[hf + 2]);
                }
            }
        }

        // ---- causal mask (last two tiles only) ----
        const int j0 = t * 64;
        if (t >= ntiles - 2) {
            #pragma unroll
            for (int nj = 0; nj < 8; nj++) {
                const int c0 = j0 + nj * 8 + 2 * t4;
                if (c0     > rg0) sc[nj][0] = -1e30f;
                if (c0 + 1 > rg0) sc[nj][1] = -1e30f;
                if (c0     > rg1) sc[nj][2] = -1e30f;
                if (c0 + 1 > rg1) sc[nj][3] = -1e30f;
            }
        }

        // ---- online softmax ----
        float mx0 = -1e30f, mx1 = -1e30f;
        #pragma unroll
        for (int nj = 0; nj < 8; nj++) {
            mx0 = fmaxf(mx0, fmaxf(sc[nj][0], sc[nj][1]));
            mx1 = fmaxf(mx1, fmaxf(sc[nj][2], sc[nj][3]));
        }
        mx0 = fmaxf(mx0, __shfl_xor_sync(0xffffffffu, mx0, 1));
        mx0 = fmaxf(mx0, __shfl_xor_sync(0xffffffffu, mx0, 2));
        mx1 = fmaxf(mx1, __shfl_xor_sync(0xffffffffu, mx1, 1));
        mx1 = fmaxf(mx1, __shfl_xor_sync(0xffffffffu, mx1, 2));
        const float mn0 = fmaxf(m0, mx0), mn1 = fmaxf(m1, mx1);
        const float cr0 = __expf(m0 - mn0), cr1 = __expf(m1 - mn1);
        m0 = mn0; m1 = mn1;
        float rs0 = 0.f, rs1 = 0.f;
        #pragma unroll
        for (int nj = 0; nj < 8; nj++) {
            sc[nj][0] = __expf(sc[nj][0] - mn0);
            sc[nj][1] = __expf(sc[nj][1] - mn0);
            sc[nj][2] = __expf(sc[nj][2] - mn1);
            sc[nj][3] = __expf(sc[nj][3] - mn1);
            rs0 += sc[nj][0] + sc[nj][1];
            rs1 += sc[nj][2] + sc[nj][3];
        }
        rs0 += __shfl_xor_sync(0xffffffffu, rs0, 1);
        rs0 += __shfl_xor_sync(0xffffffffu, rs0, 2);
        rs1 += __shfl_xor_sync(0xffffffffu, rs1, 1);
        rs1 += __shfl_xor_sync(0xffffffffu, rs1, 2);
        l0 = l0 * cr0 + rs0;
        l1 = l1 * cr1 + rs1;
        #pragma unroll
        for (int f = 0; f < 16; f++) {
            oa[f][0] *= cr0; oa[f][1] *= cr0;
            oa[f][2] *= cr1; oa[f][3] *= cr1;
        }

        // ---- O += P V (3-term) ----
        #pragma unroll
        for (int kc = 0; kc < 4; kc++) {
            uint32_t ph[4], pl[4];
            pack_hilo(sc[2 * kc][0],     sc[2 * kc][1],     ph[0], pl[0]);
            pack_hilo(sc[2 * kc][2],     sc[2 * kc][3],     ph[1], pl[1]);
            pack_hilo(sc[2 * kc + 1][0], sc[2 * kc + 1][1], ph[2], pl[2]);
            pack_hilo(sc[2 * kc + 1][2], sc[2 * kc + 1][3], ph[3], pl[3]);
            #pragma unroll
            for (int dn = 0; dn < 8; dn++) {
                uint32_t vh4[4], vl4[4];
                const uint32_t ov = sv + (uint32_t)((kc * 16 + lrow) * LDA_ + dn * 16 + lcol8) * 2;
                LDSM_X4_T(vh4, ov);
                LDSM_X4_T(vl4, ov + (uint32_t)KEL * 2);
                mma_bf16(oa[2 * dn],     ph, vh4[0], vh4[1]);
                mma_bf16(oa[2 * dn],     ph, vl4[0], vl4[1]);
                mma_bf16(oa[2 * dn],     pl, vh4[0], vh4[1]);
                mma_bf16(oa[2 * dn + 1], ph, vh4[2], vh4[3]);
                mma_bf16(oa[2 * dn + 1], ph, vl4[2], vl4[3]);
                mma_bf16(oa[2 * dn + 1], pl, vh4[2], vh4[3]);
            }
        }
        __syncthreads();
    }

    // ---- epilogue: normalize, split to bf16 hi/lo, store [b, s, h*128+d] ----
    const float i0 = 1.f / l0, i1 = 1.f / l1;
    const int r0 = q0 + wid * 16 + g;
    #pragma unroll
    for (int f = 0; f < 16; f++) {
        const int col = f * 8 + 2 * t4;
        const size_t o0 = ((size_t)b * S_ + r0) * H_ + h * HD_ + col;
        const size_t o1 = ((size_t)b * S_ + r0 + 8) * H_ + h * HD_ + col;
        uint32_t hv, lv;
        pack_hilo(oa[f][0] * i0, oa[f][1] * i0, hv, lv);
        *reinterpret_cast<uint32_t*>(g_ao_hi + o0) = hv;
        *reinterpret_cast<uint32_t*>(g_ao_lo + o0) = lv;
        pack_hilo(oa[f][2] * i1, oa[f][3] * i1, hv, lv);
        *reinterpret_cast<uint32_t*>(g_ao_hi + o1) = hv;
        *reinterpret_cast<uint32_t*>(g_ao_lo + o1) = lv;
    }
}

// ---------------------------------------------------------------------------
extern "C" void kernel_launch(void* const* d_in, const int* in_sizes, int n_in,
                              void* d_out, int out_size)
{
    (void)in_sizes; (void)n_in; (void)out_size;
    const float* hidden = (const float*)d_in[0];
    // d_in[1] = attention_mask: deterministic causal mask, implemented directly.
    const float* w_pack = (const float*)d_in[2];
    const float* w_o    = (const float*)d_in[3];
    float* out = (float*)d_out;

    cudaFuncSetAttribute(gemm_mma<0>, cudaFuncAttributeMaxDynamicSharedMemorySize, GEMM_SMEM);
    cudaFuncSetAttribute(gemm_mma<1>, cudaFuncAttributeMaxDynamicSharedMemorySize, GEMM_SMEM);
    cudaFuncSetAttribute(attn_mma, cudaFuncAttributeMaxDynamicSharedMemorySize, ATTN_SMEM);

    __nv_bfloat16 *h_hi, *h_lo, *wp_hi, *wp_lo, *wo_hi, *wo_lo, *ao_hi, *ao_lo;
    cudaGetSymbolAddress((void**)&h_hi,  g_h_hi);  cudaGetSymbolAddress((void**)&h_lo,  g_h_lo);
    cudaGetSymbolAddress((void**)&wp_hi, g_wp_hi); cudaGetSymbolAddress((void**)&wp_lo, g_wp_lo);
    cudaGetSymbolAddress((void**)&wo_hi, g_wo_hi); cudaGetSymbolAddress((void**)&wo_lo, g_wo_lo);
    cudaGetSymbolAddress((void**)&ao_hi, g_ao_hi); cudaGetSymbolAddress((void**)&ao_lo, g_ao_lo);

    const int M = B_ * S_;                       // 4096
    const int n_hidden = M * H_;
    const int n_wp = 3 * H_ * H_;
    const int n_wo = H_ * H_;

    split_kernel<<<(n_hidden / 4 + 255) / 256, 256>>>(hidden, h_hi, h_lo, n_hidden / 4);
    split_kernel<<<(n_wp / 4 + 255) / 256, 256>>>(w_pack, wp_hi, wp_lo, n_wp / 4);
    split_kernel<<<(n_wo / 4 + 255) / 256, 256>>>(w_o, wo_hi, wo_lo, n_wo / 4);

    // K1: QKV projection -> q/k/v bf16 hi/lo (q pre-scaled by 1/sqrt(128))
    dim3 g1((3 * H_) / 64, M / 128);             // (96, 32)
    gemm_mma<0><<<g1, 256, GEMM_SMEM>>>(h_hi, h_lo, wp_hi, wp_lo, nullptr, 3 * H_, H_);

    // K2: causal flash attention (bf16 mma 3-term) -> g_ao hi/lo
    dim3 g2(S_ / 128, NH_, B_);                  // (16, 16, 2)
    attn_mma<<<g2, 256, ATTN_SMEM>>>();

    // K3: output projection -> d_out (fp32)
    dim3 g3(H_ / 64, M / 128);                   // (32, 32)
    gemm_mma<1><<<g3, 256, GEMM_SMEM>>>(ao_hi, ao_lo, wo_hi, wo_lo, out, H_, H_);
}